// round 2
// baseline (speedup 1.0000x reference)
#include <cuda_runtime.h>
#include <math.h>
#include <stdint.h>

#define N_NODES 50000
#define N_EDGES 800000
#define EPS 0.01f
#define NSTEPS 10

// ---------------- scratch ----------------
__device__ float  g_B[256 * 192];          // packed [Wt1 | Ws | Wd], row-major [k][j]
__device__ float  g_hid[N_NODES * 128];
__device__ float  g_hs[N_NODES * 32];
__device__ float  g_hd[N_NODES * 32];
__device__ int    g_cnt[N_NODES];
__device__ int    g_off[N_NODES + 1];
__device__ int    g_pos[N_EDGES];          // original edge -> CSR slot
__device__ float4 g_ce[N_EDGES];           // CSR slot: {src_as_float, elen, step, -}
__device__ float4 g_coordsA[N_NODES];
__device__ float4 g_coordsB[N_NODES];

__device__ __forceinline__ float lrelu(float x) { return x > 0.f ? x : 0.01f * x; }

// packed fp32x2 helpers (Blackwell 2x fp32 path)
__device__ __forceinline__ uint64_t pk2(float x) {
    uint64_t r; asm("mov.b64 %0, {%1, %1};" : "=l"(r) : "f"(x)); return r;
}
__device__ __forceinline__ void fma2(uint64_t& d, uint64_t a, uint64_t b) {
    asm("fma.rn.f32x2 %0, %1, %2, %0;" : "+l"(d) : "l"(a), "l"(b));
}
__device__ __forceinline__ float2 up2(uint64_t v) {
    float2 f; asm("mov.b64 {%0, %1}, %2;" : "=f"(f.x), "=f"(f.y) : "l"(v)); return f;
}

// ---------------- init: pack B, load coords, zero counts ----------------
__global__ void init_k(const float* __restrict__ cart,
                       const float* __restrict__ Wt1,
                       const float* __restrict__ Wr1) {
    int i = blockIdx.x * blockDim.x + threadIdx.x;
    if (i < N_NODES) {
        g_coordsA[i] = make_float4(cart[3*i], cart[3*i+1], cart[3*i+2], 0.f);
        g_cnt[i] = 0;
    }
    if (i < 256 * 192) {
        int k = i / 192, j = i % 192;
        float v;
        if (j < 128)      v = Wt1[k * 128 + j];
        else if (j < 160) v = Wr1[(64  + k) * 32 + (j - 128)];
        else              v = Wr1[(320 + k) * 32 + (j - 160)];
        g_B[i] = v;
    }
}

// ---------------- CSR build ----------------
__global__ void count_k(const int* __restrict__ eidx) {
    int e = blockIdx.x * blockDim.x + threadIdx.x;
    if (e < N_EDGES) atomicAdd(&g_cnt[eidx[N_EDGES + e]], 1);
}

__global__ void scan_k() {
    __shared__ int part[1024];
    const int t = threadIdx.x;
    const int CH = (N_NODES + 1023) / 1024;   // 49
    int base = t * CH;
    int sum = 0;
    for (int j = 0; j < CH; j++) {
        int idx = base + j;
        if (idx < N_NODES) sum += g_cnt[idx];
    }
    part[t] = sum;
    __syncthreads();
    for (int off = 1; off < 1024; off <<= 1) {
        int v = (t >= off) ? part[t - off] : 0;
        __syncthreads();
        part[t] += v;
        __syncthreads();
    }
    int prefix = (t == 0) ? 0 : part[t - 1];
    for (int j = 0; j < CH; j++) {
        int idx = base + j;
        if (idx < N_NODES) {
            g_off[idx] = prefix;
            prefix += g_cnt[idx];
            g_cnt[idx] = 0;                  // reset for scatter cursor
        }
    }
    if (t == 1023) g_off[N_NODES] = part[1023];
}

__global__ void scatter_k(const int* __restrict__ eidx) {
    int e = blockIdx.x * blockDim.x + threadIdx.x;
    if (e >= N_EDGES) return;
    int s = eidx[e];
    int d = eidx[N_EDGES + e];
    int pos = g_off[d] + atomicAdd(&g_cnt[d], 1);
    g_pos[e] = pos;
    ((float*)g_ce)[pos * 4 + 0] = __int_as_float(s);
}

// ---------------- fused node GEMM: [M,256] x [256,192], f32x2 ----------------
// Tile 64 x 192, BK=16, 128 threads; per-thread 8 rows x 6 col-pairs.
__global__ void node_gemm(const float* __restrict__ A, const float* __restrict__ bt1) {
    __shared__ float As[16 * 68];     // [k][m], pad 68
    __shared__ float Bs[16 * 192];    // [k][j]

    const int t  = threadIdx.x;
    const int tx = t & 15;            // 16 col-groups of 12
    const int ty = t >> 4;            // 8 row-groups of 8
    const int m0 = blockIdx.x * 64;

    uint64_t acc[48];
#pragma unroll
    for (int i = 0; i < 48; i++) acc[i] = 0ull;

    for (int kt = 0; kt < 16; kt++) {
        // fill As (transposed): 64 rows x 16 k = 256 float4, 2 per thread
#pragma unroll
        for (int i = 0; i < 2; i++) {
            int f = t + 128 * i;
            int m = f >> 2, kq = f & 3;
            float4 v = make_float4(0.f, 0.f, 0.f, 0.f);
            if (m0 + m < N_NODES)
                v = *(const float4*)(A + (size_t)(m0 + m) * 256 + kt * 16 + kq * 4);
            As[(kq*4 + 0) * 68 + m] = v.x;
            As[(kq*4 + 1) * 68 + m] = v.y;
            As[(kq*4 + 2) * 68 + m] = v.z;
            As[(kq*4 + 3) * 68 + m] = v.w;
        }
        // fill Bs: 16 x 192 = 768 float4, 6 per thread
        const float4* B4 = (const float4*)(g_B + kt * 16 * 192);
        float4* Bs4 = (float4*)Bs;
#pragma unroll
        for (int i = 0; i < 6; i++) Bs4[t + 128 * i] = B4[t + 128 * i];
        __syncthreads();

#pragma unroll
        for (int kk = 0; kk < 16; kk++) {
            const float4* As4 = (const float4*)&As[kk * 68 + ty * 8];
            float4 a0 = As4[0], a1 = As4[1];
            uint64_t av[8];
            av[0] = pk2(a0.x); av[1] = pk2(a0.y); av[2] = pk2(a0.z); av[3] = pk2(a0.w);
            av[4] = pk2(a1.x); av[5] = pk2(a1.y); av[6] = pk2(a1.z); av[7] = pk2(a1.w);
            const ulonglong2* w4 = (const ulonglong2*)&Bs[kk * 192 + tx * 12];
            ulonglong2 b01 = w4[0], b23 = w4[1], b45 = w4[2];
            uint64_t bv[6] = {b01.x, b01.y, b23.x, b23.y, b45.x, b45.y};
#pragma unroll
            for (int r = 0; r < 8; r++)
#pragma unroll
                for (int c = 0; c < 6; c++) fma2(acc[r*6 + c], av[r], bv[c]);
        }
        __syncthreads();
    }

#pragma unroll
    for (int r = 0; r < 8; r++) {
        int m = m0 + ty * 8 + r;
        if (m >= N_NODES) continue;
#pragma unroll
        for (int c = 0; c < 6; c++) {
            float2 v = up2(acc[r*6 + c]);
            int col = tx * 12 + c * 2;
#pragma unroll
            for (int q = 0; q < 2; q++) {
                float val = q ? v.y : v.x;
                int cc = col + q;
                if (cc < 128)      g_hid[m * 128 + cc] = lrelu(val + __ldg(&bt1[cc]));
                else if (cc < 160) g_hs[m * 32 + (cc - 128)] = val;
                else               g_hd[m * 32 + (cc - 160)] = val;
            }
        }
    }
}

// ---------------- torsion finisher: warp per node ----------------
__global__ void torsion_k(const float* __restrict__ Wt2,
                          const float* __restrict__ bt2,
                          float* __restrict__ out) {
    int warp = (blockIdx.x * blockDim.x + threadIdx.x) >> 5;
    int lane = threadIdx.x & 31;
    if (warp >= N_NODES) return;

    float4 h = *(const float4*)(g_hid + warp * 128 + lane * 4);
    int base = (lane * 4) * 3;
    float t0 = h.x * __ldg(&Wt2[base+0]) + h.y * __ldg(&Wt2[base+3])
             + h.z * __ldg(&Wt2[base+6]) + h.w * __ldg(&Wt2[base+9]);
    float t1 = h.x * __ldg(&Wt2[base+1]) + h.y * __ldg(&Wt2[base+4])
             + h.z * __ldg(&Wt2[base+7]) + h.w * __ldg(&Wt2[base+10]);
    float t2 = h.x * __ldg(&Wt2[base+2]) + h.y * __ldg(&Wt2[base+5])
             + h.z * __ldg(&Wt2[base+8]) + h.w * __ldg(&Wt2[base+11]);

#pragma unroll
    for (int off = 16; off > 0; off >>= 1) {
        t0 += __shfl_down_sync(0xffffffffu, t0, off);
        t1 += __shfl_down_sync(0xffffffffu, t1, off);
        t2 += __shfl_down_sync(0xffffffffu, t2, off);
    }
    if (lane == 0) {
        t0 += __ldg(&bt2[0]); t1 += __ldg(&bt2[1]); t2 += __ldg(&bt2[2]);
        float rho = sqrtf(t0*t0 + t1*t1 + t2*t2);
        float theta = (fabsf(t0) > fabsf(t1)) ? atan2f(t1, t0)
                                              : (1.57079632679489662f - atan2f(t0, t1));
        float tn2 = t2 / rho;
        tn2 = fminf(fmaxf(tn2, -1.0f + EPS), 1.0f - EPS);
        float phi = acosf(tn2);
        float* o = out + 3 * N_NODES + warp * 3;
        o[0] = rho; o[1] = phi; o[2] = theta;
    }
}

// ---------------- edge MLP: thread-per-edge, f32x2, 128 edges/block ----------------
__global__ void edge_mlp(const float* __restrict__ Eemb,
                         const float* __restrict__ Wr1,
                         const float* __restrict__ br1,
                         const float* __restrict__ Wr2,
                         const float* __restrict__ br2,
                         const int* __restrict__ eidx) {
    __shared__ float Ae[64 * 132];    // [k][e], pad 132
    __shared__ float Ws[64 * 32];     // We rows 0..63 of Wr1
    __shared__ float Wr2s[64];

    const int t    = threadIdx.x;     // 128
    const int base = blockIdx.x * 128;

    {
        float4* Ws4 = (float4*)Ws;
        const float4* W14 = (const float4*)Wr1;
#pragma unroll
        for (int i = 0; i < 4; i++) Ws4[t + 128 * i] = W14[t + 128 * i];
        if (t < 64) Wr2s[t] = Wr2[t];
    }
    {   // fill Ae transposed: 128 edges x 64 k = 2048 float4-chunks of 4k
        const float4* E4 = (const float4*)(Eemb + (size_t)base * 64);
#pragma unroll
        for (int i = 0; i < 16; i++) {
            int g = t + 128 * i;
            int e = g >> 4, k4 = g & 15;
            float4 v = E4[g];
            Ae[(k4*4 + 0) * 132 + e] = v.x;
            Ae[(k4*4 + 1) * 132 + e] = v.y;
            Ae[(k4*4 + 2) * 132 + e] = v.z;
            Ae[(k4*4 + 3) * 132 + e] = v.w;
        }
    }
    __syncthreads();

    uint64_t acc[16];
#pragma unroll
    for (int c = 0; c < 16; c++) acc[c] = 0ull;

#pragma unroll 8
    for (int k = 0; k < 64; k++) {
        uint64_t a2 = pk2(Ae[k * 132 + t]);
        const ulonglong2* w4 = (const ulonglong2*)&Ws[k * 32];
#pragma unroll
        for (int c8 = 0; c8 < 8; c8++) {
            ulonglong2 bb = w4[c8];
            fma2(acc[2*c8 + 0], a2, bb.x);
            fma2(acc[2*c8 + 1], a2, bb.y);
        }
    }

    const int e = base + t;
    const int s = __ldg(&eidx[e]);
    const int d = __ldg(&eidx[N_EDGES + e]);

    float h[32];
#pragma unroll
    for (int c = 0; c < 16; c++) {
        float2 v = up2(acc[c]);
        h[2*c] = v.x; h[2*c + 1] = v.y;
    }
#pragma unroll
    for (int q = 0; q < 8; q++) {
        float4 hsv = *(const float4*)&g_hs[s * 32 + q * 4];
        float4 hdv = *(const float4*)&g_hd[d * 32 + q * 4];
        float4 bb  = *(const float4*)&br1[q * 4];
        h[q*4+0] += hsv.x + hdv.x + bb.x;
        h[q*4+1] += hsv.y + hdv.y + bb.y;
        h[q*4+2] += hsv.z + hdv.z + bb.z;
        h[q*4+3] += hsv.w + hdv.w + bb.w;
    }
    float p0 = 0.f, p1 = 0.f;
#pragma unroll
    for (int c = 0; c < 32; c++) {
        float hh = lrelu(h[c]);
        p0 = fmaf(hh, Wr2s[c * 2 + 0], p0);
        p1 = fmaf(hh, Wr2s[c * 2 + 1], p1);
    }
    float elx = p0 + __ldg(&br2[0]) + 1.0f;
    float elen = (elx > 20.f) ? elx : log1pf(expf(elx));
    float stx = p1 + __ldg(&br2[1]) - 2.0f;
    float step = 1.0f / (1.0f + expf(-stx));
    int pos = g_pos[e];
    ((float*)g_ce)[pos * 4 + 1] = elen;
    ((float*)g_ce)[pos * 4 + 2] = step;
}

// ---------------- fused refiner iteration: 16 lanes per node ----------------
__global__ void refine_k(const float4* __restrict__ cur,
                         float4* __restrict__ nxt,
                         float* __restrict__ out, int write_out) {
    int warp = (blockIdx.x * blockDim.x + threadIdx.x) >> 5;
    int lane = threadIdx.x & 31;
    int n = warp * 2 + (lane >> 4);
    int g = lane & 15;
    if (n >= N_NODES) return;

    int off = g_off[n], end = g_off[n + 1];
    float4 cd = __ldg(&cur[n]);
    float fx = 0.f, fy = 0.f, fz = 0.f;
    for (int j = off + g; j < end; j += 16) {
        float4 ce = __ldg(&g_ce[j]);
        int s = __float_as_int(ce.x);
        float4 cs = __ldg(&cur[s]);
        float dx = cd.x - cs.x, dy = cd.y - cs.y, dz = cd.z - cs.z;
        float dist = sqrtf(dx*dx + dy*dy + dz*dz);
        float coef = 2.0f * ce.z * (ce.y - dist) / (dist + EPS);
        fx += coef * dx; fy += coef * dy; fz += coef * dz;
    }
#pragma unroll
    for (int o = 8; o > 0; o >>= 1) {
        fx += __shfl_xor_sync(0xffffffffu, fx, o);
        fy += __shfl_xor_sync(0xffffffffu, fy, o);
        fz += __shfl_xor_sync(0xffffffffu, fz, o);
    }
    if (g == 0) {
        float an = sqrtf(fx*fx + fy*fy + fz*fz) + EPS;
        float sc = fminf(an, 0.5f) / an;
        float4 c = cd;
        c.x += fx * sc; c.y += fy * sc; c.z += fz * sc;
        nxt[n] = c;
        if (write_out) {
            out[n * 3 + 0] = c.x;
            out[n * 3 + 1] = c.y;
            out[n * 3 + 2] = c.z;
        }
    }
}

// ---------------- launch ----------------
extern "C" void kernel_launch(void* const* d_in, const int* in_sizes, int n_in,
                              void* d_out, int out_size) {
    const float* node_emb = (const float*)d_in[0];
    const float* edge_emb = (const float*)d_in[1];
    const float* cart     = (const float*)d_in[2];
    const float* Wt1      = (const float*)d_in[3];
    const float* bt1      = (const float*)d_in[4];
    const float* Wt2      = (const float*)d_in[5];
    const float* bt2      = (const float*)d_in[6];
    const float* Wr1      = (const float*)d_in[7];
    const float* br1      = (const float*)d_in[8];
    const float* Wr2      = (const float*)d_in[9];
    const float* br2      = (const float*)d_in[10];
    const int*   eidx     = (const int*)d_in[11];
    float* out = (float*)d_out;

    float4 *cA, *cB;
    cudaGetSymbolAddress((void**)&cA, g_coordsA);
    cudaGetSymbolAddress((void**)&cB, g_coordsB);

    init_k<<<(N_NODES + 255) / 256, 256>>>(cart, Wt1, Wr1);
    count_k<<<(N_EDGES + 255) / 256, 256>>>(eidx);
    scan_k<<<1, 1024>>>();
    scatter_k<<<(N_EDGES + 255) / 256, 256>>>(eidx);
    node_gemm<<<(N_NODES + 63) / 64, 128>>>(node_emb, bt1);
    torsion_k<<<N_NODES / 4, 128>>>(Wt2, bt2, out);
    edge_mlp<<<N_EDGES / 128, 128>>>(edge_emb, Wr1, br1, Wr2, br2, eidx);
    for (int it = 0; it < NSTEPS; it++) {
        const float4* cur = (it & 1) ? cB : cA;
        float4*       nxt = (it & 1) ? cA : cB;
        refine_k<<<(N_NODES * 16 + 255) / 256, 256>>>(cur, nxt, out, it == NSTEPS - 1);
    }
}